// round 2
// baseline (speedup 1.0000x reference)
#include <cuda_runtime.h>
#include <cuda_bf16.h>

#define BB 4
#define NQ 4096
#define NC 4096
#define DY 8
#define SPLITS 4
#define CHUNK (NC / SPLITS)   // 1024 contexts per CTA
#define QTILE 256

// Scratch for split-K partial sums: [SPLITS][B*NQ][9]
__device__ float g_partial[(size_t)SPLITS * BB * NQ * (DY + 1)];

__global__ __launch_bounds__(256) void setconv_part(
    const float* __restrict__ xq,
    const float* __restrict__ xc,
    const float* __restrict__ yc,
    const float* __restrict__ lls)
{
    __shared__ float2 sx[CHUNK];        // pre-scaled context coords (8 KB)
    __shared__ float4 sy[CHUNK * 2];    // context y values (32 KB)

    const int b = blockIdx.y;
    const int z = blockIdx.z;
    const int q = blockIdx.x * QTILE + threadIdx.x;

    // scale factor: s = sqrt(log2(e)/2) * exp(-log_length_scale)
    // so that exp(-d2/(2*ls^2)) == exp2(-((s*dx)^2 + (s*dy)^2))
    const float s = 0.84932184f * __expf(-lls[0]);

    // Stage context chunk into SMEM (x pre-scaled)
    const float* xcb = xc + ((size_t)b * NC + (size_t)z * CHUNK) * 2;
    const float* ycb = yc + ((size_t)b * NC + (size_t)z * CHUNK) * DY;
    for (int i = threadIdx.x; i < CHUNK / 2; i += 256) {
        float4 v = reinterpret_cast<const float4*>(xcb)[i];
        sx[2 * i]     = make_float2(v.x * s, v.y * s);
        sx[2 * i + 1] = make_float2(v.z * s, v.w * s);
    }
    for (int i = threadIdx.x; i < CHUNK * 2; i += 256) {
        sy[i] = reinterpret_cast<const float4*>(ycb)[i];
    }

    const float qx = xq[((size_t)b * NQ + q) * 2 + 0] * s;
    const float qy = xq[((size_t)b * NQ + q) * 2 + 1] * s;

    __syncthreads();

    float a0 = 0.f, a1 = 0.f, a2 = 0.f, a3 = 0.f;
    float a4 = 0.f, a5 = 0.f, a6 = 0.f, a7 = 0.f;
    float aw = 0.f;

    #pragma unroll 8
    for (int c = 0; c < CHUNK; c++) {
        float2 p  = sx[c];
        float4 ya = sy[2 * c];
        float4 yb = sy[2 * c + 1];
        float dx = qx - p.x;
        float dy = qy - p.y;
        float t  = fmaf(dx, dx, dy * dy);
        float w;
        asm("ex2.approx.ftz.f32 %0, %1;" : "=f"(w) : "f"(-t));
        a0 = fmaf(w, ya.x, a0);
        a1 = fmaf(w, ya.y, a1);
        a2 = fmaf(w, ya.z, a2);
        a3 = fmaf(w, ya.w, a3);
        a4 = fmaf(w, yb.x, a4);
        a5 = fmaf(w, yb.y, a5);
        a6 = fmaf(w, yb.z, a6);
        a7 = fmaf(w, yb.w, a7);
        aw += w;
    }

    float* out = g_partial + (((size_t)z * BB + b) * NQ + q) * (DY + 1);
    out[0] = a0; out[1] = a1; out[2] = a2; out[3] = a3;
    out[4] = a4; out[5] = a5; out[6] = a6; out[7] = a7;
    out[8] = aw;
}

__global__ __launch_bounds__(256) void setconv_reduce(float* __restrict__ out)
{
    const int i = blockIdx.x * 256 + threadIdx.x;   // 0 .. B*NQ-1
    float acc[DY + 1];
    #pragma unroll
    for (int j = 0; j < DY + 1; j++) acc[j] = 0.f;

    #pragma unroll
    for (int z = 0; z < SPLITS; z++) {
        const float* p = g_partial + ((size_t)z * BB * NQ + i) * (DY + 1);
        #pragma unroll
        for (int j = 0; j < DY + 1; j++) acc[j] += p[j];
    }

    const float inv = 1.0f / (acc[DY] + 1e-8f);
    float* o = out + (size_t)i * (DY + 1);
    #pragma unroll
    for (int j = 0; j < DY; j++) o[j] = acc[j] * inv;
    o[DY] = acc[DY];
}

extern "C" void kernel_launch(void* const* d_in, const int* in_sizes, int n_in,
                              void* d_out, int out_size) {
    const float* xq  = (const float*)d_in[0];
    const float* xc  = (const float*)d_in[1];
    const float* yc  = (const float*)d_in[2];
    const float* lls = (const float*)d_in[3];
    float* out = (float*)d_out;

    dim3 grid(NQ / QTILE, BB, SPLITS);
    setconv_part<<<grid, 256>>>(xq, xc, yc, lls);
    setconv_reduce<<<(BB * NQ) / 256, 256>>>(out);
}

// round 3
// speedup vs baseline: 1.1873x; 1.1873x over previous
#include <cuda_runtime.h>
#include <cuda_bf16.h>
#include <cstdint>

#define BB 4
#define NQ 4096
#define NC 4096
#define DY 8
#define SPLITS 8
#define CHUNK (NC / SPLITS)   // 512 contexts per CTA
#define QTILE 128

// Scratch for split-K partial sums: [SPLITS][B*NQ][9]
#define PSTRIDE ((size_t)BB * NQ * (DY + 1))
__device__ float g_partial[(size_t)SPLITS * PSTRIDE];

__device__ __forceinline__ uint64_t addx2(uint64_t a, uint64_t b) {
    uint64_t r; asm("add.rn.f32x2 %0, %1, %2;" : "=l"(r) : "l"(a), "l"(b)); return r;
}
__device__ __forceinline__ uint64_t mulx2(uint64_t a, uint64_t b) {
    uint64_t r; asm("mul.rn.f32x2 %0, %1, %2;" : "=l"(r) : "l"(a), "l"(b)); return r;
}
__device__ __forceinline__ uint64_t fmax2(uint64_t a, uint64_t b, uint64_t c) {
    uint64_t r; asm("fma.rn.f32x2 %0, %1, %2, %3;" : "=l"(r) : "l"(a), "l"(b), "l"(c)); return r;
}

__global__ __launch_bounds__(QTILE) void setconv_part(
    const float* __restrict__ xq,
    const float* __restrict__ xc,
    const float* __restrict__ yc,
    const float* __restrict__ lls)
{
    __shared__ uint64_t sx[CHUNK];       // pre-scaled, pre-negated context coords (4 KB)
    __shared__ ulonglong2 sy[CHUNK * 2]; // context y values (16 KB)

    const int b = blockIdx.y;
    const int z = blockIdx.z;
    const int q = blockIdx.x * QTILE + threadIdx.x;

    // s = sqrt(log2(e)/2) / length_scale, so exp(-d2/(2 ls^2)) = exp2(-((s dx)^2 + (s dy)^2))
    const float s = 0.84932184f * __expf(-lls[0]);

    // Stage context chunk into SMEM: coords scaled by -s (negated for add.f32x2 diff)
    const float* xcb = xc + ((size_t)b * NC + (size_t)z * CHUNK) * 2;
    const float* ycb = yc + ((size_t)b * NC + (size_t)z * CHUNK) * DY;
    for (int i = threadIdx.x; i < CHUNK / 2; i += QTILE) {
        float4 v = reinterpret_cast<const float4*>(xcb)[i];
        float2 p0 = make_float2(-v.x * s, -v.y * s);
        float2 p1 = make_float2(-v.z * s, -v.w * s);
        sx[2 * i]     = *reinterpret_cast<uint64_t*>(&p0);
        sx[2 * i + 1] = *reinterpret_cast<uint64_t*>(&p1);
    }
    for (int i = threadIdx.x; i < CHUNK * 2; i += QTILE) {
        sy[i] = reinterpret_cast<const ulonglong2*>(ycb)[i];
    }

    const float qx = xq[((size_t)b * NQ + q) * 2 + 0] * s;
    const float qy = xq[((size_t)b * NQ + q) * 2 + 1] * s;
    uint64_t qp;
    asm("mov.b64 %0, {%1, %2};" : "=l"(qp) : "f"(qx), "f"(qy));

    __syncthreads();

    uint64_t a01 = 0, a23 = 0, a45 = 0, a67 = 0;
    float aw = 0.f;

    #pragma unroll 8
    for (int c = 0; c < CHUNK; c++) {
        uint64_t p = sx[c];
        ulonglong2 ya = sy[2 * c];
        ulonglong2 yb = sy[2 * c + 1];
        uint64_t d  = addx2(qp, p);       // (dx, dy) * s
        uint64_t d2 = mulx2(d, d);        // (dx^2, dy^2)
        float tx, ty;
        asm("mov.b64 {%0, %1}, %2;" : "=f"(tx), "=f"(ty) : "l"(d2));
        float nt = -tx - ty;              // single FADD with negate modifiers
        float w;
        asm("ex2.approx.ftz.f32 %0, %1;" : "=f"(w) : "f"(nt));
        uint64_t wp;
        asm("mov.b64 %0, {%1, %1};" : "=l"(wp) : "f"(w));
        a01 = fmax2(wp, ya.x, a01);
        a23 = fmax2(wp, ya.y, a23);
        a45 = fmax2(wp, yb.x, a45);
        a67 = fmax2(wp, yb.y, a67);
        aw += w;
    }

    float* out = g_partial + (size_t)z * PSTRIDE + ((size_t)b * NQ + q) * (DY + 1);
    float r0, r1;
    asm("mov.b64 {%0, %1}, %2;" : "=f"(r0), "=f"(r1) : "l"(a01)); out[0] = r0; out[1] = r1;
    asm("mov.b64 {%0, %1}, %2;" : "=f"(r0), "=f"(r1) : "l"(a23)); out[2] = r0; out[3] = r1;
    asm("mov.b64 {%0, %1}, %2;" : "=f"(r0), "=f"(r1) : "l"(a45)); out[4] = r0; out[5] = r1;
    asm("mov.b64 {%0, %1}, %2;" : "=f"(r0), "=f"(r1) : "l"(a67)); out[6] = r0; out[7] = r1;
    out[8] = aw;
}

// One thread per output FLOAT (B*NQ*9 of them), fully coalesced.
__global__ __launch_bounds__(256) void setconv_reduce(float* __restrict__ out)
{
    const int gid = blockIdx.x * 256 + threadIdx.x;   // 0 .. B*NQ*9-1
    const int j = gid % 9;
    const int dbase = gid - j + 8;                    // density slot of this row

    float v = 0.f, den = 0.f;
    #pragma unroll
    for (int z = 0; z < SPLITS; z++) {
        v   += g_partial[(size_t)z * PSTRIDE + gid];
        den += g_partial[(size_t)z * PSTRIDE + dbase];
    }
    out[gid] = (j == 8) ? v : v * (1.0f / (den + 1e-8f));
}

extern "C" void kernel_launch(void* const* d_in, const int* in_sizes, int n_in,
                              void* d_out, int out_size) {
    const float* xq  = (const float*)d_in[0];
    const float* xc  = (const float*)d_in[1];
    const float* yc  = (const float*)d_in[2];
    const float* lls = (const float*)d_in[3];
    float* out = (float*)d_out;

    dim3 grid(NQ / QTILE, BB, SPLITS);
    setconv_part<<<grid, QTILE>>>(xq, xc, yc, lls);
    setconv_reduce<<<(BB * NQ * (DY + 1)) / 256, 256>>>(out);
}

// round 5
// speedup vs baseline: 2.1110x; 1.7780x over previous
#include <cuda_runtime.h>
#include <cstdint>

#define BB 4
#define NQ 4096
#define NC 4096
#define QT 128                 // queries per CTA
#define NKSTEP (NC / 8)        // 512 k-steps of K=8
#define NTHREADS 512

// dynamic smem (bytes)
#define OFF_B   0                      // B fragments: [512 ksteps][32 lanes] uint2 = 128KB
#define OFF_A   131072                 // coords A2:   [512 ksteps][4] float4   = 32KB
#define OFF_SCR 163840                 // cross-warp reduce scratch: 8KB
#define SMEM_TOTAL (OFF_SCR + 8192)    // 168KB

static __device__ __forceinline__ uint64_t addx2(uint64_t a, uint64_t b) {
    uint64_t r; asm("add.rn.f32x2 %0, %1, %2;" : "=l"(r) : "l"(a), "l"(b)); return r;
}
static __device__ __forceinline__ uint64_t mulx2(uint64_t a, uint64_t b) {
    uint64_t r; asm("mul.rn.f32x2 %0, %1, %2;" : "=l"(r) : "l"(a), "l"(b)); return r;
}
// two RBF weights sharing one context point (px,py), for queries qa, qb (packed +s*q)
static __device__ __forceinline__ void wexp2(uint64_t qa, uint64_t qb,
                                             float px, float py,
                                             float& w0, float& w1) {
    uint64_t p;
    asm("mov.b64 %0, {%1, %2};" : "=l"(p) : "f"(px), "f"(py));
    uint64_t da = addx2(qa, p);
    uint64_t db = addx2(qb, p);
    uint64_t sa = mulx2(da, da);
    uint64_t sb = mulx2(db, db);
    float ax, ay, bx, by;
    asm("mov.b64 {%0, %1}, %2;" : "=f"(ax), "=f"(ay) : "l"(sa));
    asm("mov.b64 {%0, %1}, %2;" : "=f"(bx), "=f"(by) : "l"(sb));
    asm("ex2.approx.ftz.f32 %0, %1;" : "=f"(w0) : "f"(-ax - ay));
    asm("ex2.approx.ftz.f32 %0, %1;" : "=f"(w1) : "f"(-bx - by));
}
static __device__ __forceinline__ uint32_t tf32cvt(float v) {
    uint32_t u; asm("cvt.rna.tf32.f32 %0, %1;" : "=r"(u) : "f"(v)); return u;
}
static __device__ __forceinline__ void mma8(float& c0, float& c1, float& c2, float& c3,
                                            uint32_t a0, uint32_t a1, uint32_t a2, uint32_t a3,
                                            uint32_t b0, uint32_t b1) {
    asm volatile(
        "mma.sync.aligned.m16n8k8.row.col.f32.tf32.tf32.f32 "
        "{%0,%1,%2,%3}, {%4,%5,%6,%7}, {%8,%9}, {%0,%1,%2,%3};"
        : "+f"(c0), "+f"(c1), "+f"(c2), "+f"(c3)
        : "r"(a0), "r"(a1), "r"(a2), "r"(a3), "r"(b0), "r"(b1));
}

__global__ void __launch_bounds__(NTHREADS, 1)
setconv_hmma(const float* __restrict__ xq, const float* __restrict__ xc,
             const float* __restrict__ yc, const float* __restrict__ lls,
             float* __restrict__ out)
{
    extern __shared__ char smem[];
    const int t = threadIdx.x;
    const int wid = t >> 5;
    const int lane = t & 31;

    const int b  = blockIdx.x >> 5;
    const int qt = blockIdx.x & 31;

    // s = sqrt(log2(e)/2) / length_scale -> exp(-d2/(2 ls^2)) = exp2(-|s*d|^2)
    const float s = 0.84932184f * __expf(-lls[0]);

    // ---- stage whole K into SMEM ----
    // B fragments: B'[ks][lane] = (tf32(Y[c0+(l&3)][l>>2]), tf32(Y[c0+4+(l&3)][l>>2]))
    {
        const float* Yb = yc + (size_t)b * NC * 8;
        uint2* Bp = (uint2*)(smem + OFF_B);
        #pragma unroll 4
        for (int e = t; e < NKSTEP * 32; e += NTHREADS) {
            int ks = e >> 5, l = e & 31;
            int c0 = ks * 8;
            float v0 = Yb[(size_t)(c0 + (l & 3)) * 8 + (l >> 2)];
            float v1 = Yb[(size_t)(c0 + 4 + (l & 3)) * 8 + (l >> 2)];
            Bp[e] = make_uint2(tf32cvt(v0), tf32cvt(v1));
        }
        // coords: A2[ks][j] = float4(-s*x_{c0+j}, -s*y_{c0+j}, -s*x_{c0+j+4}, -s*y_{c0+j+4})
        const float2* Xb = (const float2*)(xc + (size_t)b * NC * 2);
        float2* Ap2 = (float2*)(smem + OFF_A);
        #pragma unroll 4
        for (int i = t; i < NC; i += NTHREADS) {
            float2 p = Xb[i];
            int ks = i >> 3, j = i & 3, h = (i >> 2) & 1;
            Ap2[ks * 8 + j * 2 + h] = make_float2(-p.x * s, -p.y * s);
        }
    }

    // per-thread fixed queries: q_a = l>>2, q_b = q_a+8 within this warp's 16-q group
    const int g = wid & 7;                 // q-group 0..7
    const int half = wid >> 3;             // K-half 0/1
    const int qa_loc = g * 16 + (lane >> 2);
    const int qga = ((size_t)0, qt * QT + qa_loc);
    const float qax = xq[((size_t)b * NQ + qga) * 2 + 0] * s;
    const float qay = xq[((size_t)b * NQ + qga) * 2 + 1] * s;
    const float qbx = xq[((size_t)b * NQ + qga + 8) * 2 + 0] * s;
    const float qby = xq[((size_t)b * NQ + qga + 8) * 2 + 1] * s;
    uint64_t qa, qb;
    asm("mov.b64 %0, {%1, %2};" : "=l"(qa) : "f"(qax), "f"(qay));
    asm("mov.b64 %0, {%1, %2};" : "=l"(qb) : "f"(qbx), "f"(qby));

    // constant B fragment for the ones-row mma (feature col 8 == density)
    const uint32_t bones = ((lane >> 2) == 0) ? 0x3F800000u : 0u;

    __syncthreads();

    float c0 = 0.f, c1 = 0.f, c2 = 0.f, c3 = 0.f;     // features
    float e0 = 0.f, e1 = 0.f, e2 = 0.f, e3 = 0.f;     // density (cols 8..15)

    const float4* Ap = (const float4*)(smem + OFF_A);
    const uint2*  Bp = (const uint2*)(smem + OFF_B);
    const int kbeg = half * (NKSTEP / 2);
    const int kend = kbeg + (NKSTEP / 2);

    #pragma unroll 4
    for (int ks = kbeg; ks < kend; ks++) {
        float4 pc = Ap[ks * 4 + (lane & 3)];          // broadcast within quad
        uint2 bb = Bp[ks * 32 + lane];
        float w0, w1, w2, w3;
        wexp2(qa, qb, pc.x, pc.y, w0, w1);            // contexts c0+(l&3)
        wexp2(qa, qb, pc.z, pc.w, w2, w3);            // contexts c0+4+(l&3)
        uint32_t a0 = __float_as_uint(w0);            // HW truncates f32->tf32
        uint32_t a1 = __float_as_uint(w1);
        uint32_t a2 = __float_as_uint(w2);
        uint32_t a3 = __float_as_uint(w3);
        mma8(c0, c1, c2, c3, a0, a1, a2, a3, bb.x, bb.y);
        mma8(e0, e1, e2, e3, a0, a1, a2, a3, bones, bones);
    }

    // ---- combine the two K-halves ----
    float4* scr = (float4*)(smem + OFF_SCR);
    if (half == 1) {
        scr[(g * 32 + lane) * 2 + 0] = make_float4(c0, c1, c2, c3);
        scr[(g * 32 + lane) * 2 + 1] = make_float4(e0, e2, 0.f, 0.f);
    }
    __syncthreads();
    if (half == 0) {
        float4 f = scr[(g * 32 + lane) * 2 + 0];
        float4 e = scr[(g * 32 + lane) * 2 + 1];
        c0 += f.x; c1 += f.y; c2 += f.z; c3 += f.w;
        e0 += e.x; e2 += e.y;

        // density lives on lanes with (lane&3)==0; broadcast within quad
        float da = __shfl_sync(0xffffffffu, e0, lane & ~3);
        float db = __shfl_sync(0xffffffffu, e2, lane & ~3);
        float inva = 1.0f / (da + 1e-8f);
        float invb = 1.0f / (db + 1e-8f);

        const int f0 = 2 * (lane & 3);
        float* oa = out + ((size_t)b * NQ + qt * QT + qa_loc) * 9;
        float* ob = oa + 8 * 9;
        oa[f0] = c0 * inva; oa[f0 + 1] = c1 * inva;
        ob[f0] = c2 * invb; ob[f0 + 1] = c3 * invb;
        if ((lane & 3) == 0) { oa[8] = da; ob[8] = db; }
    }
}

extern "C" void kernel_launch(void* const* d_in, const int* in_sizes, int n_in,
                              void* d_out, int out_size) {
    const float* xq  = (const float*)d_in[0];
    const float* xc  = (const float*)d_in[1];
    const float* yc  = (const float*)d_in[2];
    const float* lls = (const float*)d_in[3];
    float* out = (float*)d_out;

    cudaFuncSetAttribute(setconv_hmma, cudaFuncAttributeMaxDynamicSharedMemorySize,
                         SMEM_TOTAL);
    setconv_hmma<<<BB * (NQ / QT), NTHREADS, SMEM_TOTAL>>>(xq, xc, yc, lls, out);
}

// round 8
// speedup vs baseline: 2.3078x; 1.0932x over previous
#include <cuda_runtime.h>
#include <cstdint>

#define BB 4
#define NQ 4096
#define NC 4096
#define QT 128                 // queries per CTA
#define NKS 256                // k-steps of K=16
#define NTHREADS 512

// dynamic smem (bytes)
#define OFF_B    0                     // B frags fp16: [256 ks][32 lanes] uint2 = 64KB
#define OFF_G16  65536                 // per cpair: {2Cx0,2Cx1,2Cy0,2Cy1} = 2048*16 = 32KB
#define OFF_G8   98304                 // per cpair: {-|C0|^2, -|C1|^2}    = 2048*8  = 16KB
#define OFF_SCR  114688                // cross-half reduce scratch 8KB
#define SMEM_TOTAL (OFF_SCR + 8192)    // 120KB

static __device__ __forceinline__ uint64_t addx2(uint64_t a, uint64_t b) {
    uint64_t r; asm("add.rn.f32x2 %0, %1, %2;" : "=l"(r) : "l"(a), "l"(b)); return r;
}
static __device__ __forceinline__ uint64_t fmax2(uint64_t a, uint64_t b, uint64_t c) {
    uint64_t r; asm("fma.rn.f32x2 %0, %1, %2, %3;" : "=l"(r) : "l"(a), "l"(b), "l"(c)); return r;
}
static __device__ __forceinline__ uint64_t packf2(float lo, float hi) {
    uint64_t r; asm("mov.b64 %0, {%1, %2};" : "=l"(r) : "f"(lo), "f"(hi)); return r;
}
static __device__ __forceinline__ uint32_t packh2(float lo, float hi) {
    uint32_t r; asm("cvt.rn.f16x2.f32 %0, %1, %2;" : "=r"(r) : "f"(hi), "f"(lo)); return r;
}
// two weights (one query, one context pair) -> f16x2 A-fragment register.
// t computed in packed f32x2; exp evaluated in FULL f32 (MUFU) so only the
// weight VALUE is quantized to fp16 (unbiased), not the exponent argument.
static __device__ __forceinline__ uint32_t wpair(uint64_t cx2, uint64_t cy2, uint64_t ncc,
                                                 uint64_t Qxx, uint64_t Qyy, uint64_t Qbb) {
    uint64_t tt = addx2(Qbb, ncc);
    tt = fmax2(cx2, Qxx, tt);
    tt = fmax2(cy2, Qyy, tt);
    float lo, hi;
    asm("mov.b64 {%0, %1}, %2;" : "=f"(lo), "=f"(hi) : "l"(tt));
    float w0, w1;
    asm("ex2.approx.ftz.f32 %0, %1;" : "=f"(w0) : "f"(lo));
    asm("ex2.approx.ftz.f32 %0, %1;" : "=f"(w1) : "f"(hi));
    return packh2(w0, w1);
}
static __device__ __forceinline__ void mma16(float& c0, float& c1, float& c2, float& c3,
                                             uint32_t a0, uint32_t a1, uint32_t a2, uint32_t a3,
                                             uint32_t b0, uint32_t b1) {
    asm volatile(
        "mma.sync.aligned.m16n8k16.row.col.f32.f16.f16.f32 "
        "{%0,%1,%2,%3}, {%4,%5,%6,%7}, {%8,%9}, {%0,%1,%2,%3};"
        : "+f"(c0), "+f"(c1), "+f"(c2), "+f"(c3)
        : "r"(a0), "r"(a1), "r"(a2), "r"(a3), "r"(b0), "r"(b1));
}

__global__ void __launch_bounds__(NTHREADS, 1)
setconv_h16(const float* __restrict__ xq, const float* __restrict__ xc,
            const float* __restrict__ yc, const float* __restrict__ lls,
            float* __restrict__ out)
{
    extern __shared__ char smem[];
    const int t = threadIdx.x;
    const int wid = t >> 5;
    const int lane = t & 31;

    const int b  = blockIdx.x >> 5;
    const int qt = blockIdx.x & 31;

    // s = sqrt(log2(e)/2)/ls  ->  exp(-d2/(2 ls^2)) = exp2(-|s dx|^2 - |s dy|^2)
    const float s = 0.84932184f * __expf(-lls[0]);

    // ---- stage B fragments (fp16) ----
    {
        const float* Yb = yc + (size_t)b * NC * 8;
        uint2* Bf = (uint2*)(smem + OFF_B);
        #pragma unroll 4
        for (int e = t; e < NKS * 32; e += NTHREADS) {
            int ks = e >> 5, l = e & 31;
            int c0 = ks * 16 + 2 * (l & 3);
            int n = l >> 2;
            float y00 = Yb[(size_t)c0 * 8 + n];
            float y01 = Yb[(size_t)(c0 + 1) * 8 + n];
            float y10 = Yb[(size_t)(c0 + 8) * 8 + n];
            float y11 = Yb[(size_t)(c0 + 9) * 8 + n];
            Bf[e] = make_uint2(packh2(y00, y01), packh2(y10, y11));
        }
    }
    // ---- stage context geometry (pairwise packed, pre-scaled) ----
    {
        const float2* Xb = (const float2*)(xc + (size_t)b * NC * 2);
        float4* G16 = (float4*)(smem + OFF_G16);
        float2* G8  = (float2*)(smem + OFF_G8);
        #pragma unroll 4
        for (int p = t; p < NC / 2; p += NTHREADS) {
            float2 p0 = Xb[2 * p], p1 = Xb[2 * p + 1];
            float X0 = p0.x * s, Y0 = p0.y * s;
            float X1 = p1.x * s, Y1 = p1.y * s;
            G16[p] = make_float4(2.f * X0, 2.f * X1, 2.f * Y0, 2.f * Y1);
            G8[p]  = make_float2(-fmaf(X0, X0, Y0 * Y0), -fmaf(X1, X1, Y1 * Y1));
        }
    }

    // per-thread queries: qa = group row, qb = +8
    const int g = wid & 7;                  // q-group 0..7 (16 queries each)
    const int half = wid >> 3;              // K-half 0/1
    const int qa_loc = g * 16 + (lane >> 2);
    const int qg = qt * QT + qa_loc;
    const float qax = xq[((size_t)b * NQ + qg) * 2 + 0] * s;
    const float qay = xq[((size_t)b * NQ + qg) * 2 + 1] * s;
    const float qbx = xq[((size_t)b * NQ + qg + 8) * 2 + 0] * s;
    const float qby = xq[((size_t)b * NQ + qg + 8) * 2 + 1] * s;
    const uint64_t Qxa = packf2(qax, qax), Qya = packf2(qay, qay);
    const uint64_t Qxb = packf2(qbx, qbx), Qyb = packf2(qby, qby);
    const float ba = -fmaf(qax, qax, qay * qay);
    const float bbq = -fmaf(qbx, qbx, qby * qby);
    const uint64_t Qba = packf2(ba, ba), Qbb = packf2(bbq, bbq);

    // ones-row B fragment (density column n=0)
    const uint32_t bones = ((lane >> 2) == 0) ? 0x3C003C00u : 0u;

    __syncthreads();

    float c0 = 0.f, c1 = 0.f, c2 = 0.f, c3 = 0.f;   // features
    float e0 = 0.f, e1 = 0.f, e2 = 0.f, e3 = 0.f;   // density

    const ulonglong2* G16p = (const ulonglong2*)(smem + OFF_G16);
    const uint64_t*   G8p  = (const uint64_t*)(smem + OFF_G8);
    const uint2*      Bf   = (const uint2*)(smem + OFF_B);

    const int kbeg = half * (NKS / 2);
    const int kend = kbeg + (NKS / 2);
    const int j = lane & 3;

    #pragma unroll 8
    for (int ks = kbeg; ks < kend; ks++) {
        const int p0 = ks * 8 + j;
        ulonglong2 ga = G16p[p0];          // {cx2 pair, cy2 pair} contexts 2j,2j+1
        uint64_t   na = G8p[p0];
        ulonglong2 gb = G16p[p0 + 4];      // contexts 2j+8, 2j+9
        uint64_t   nb = G8p[p0 + 4];
        uint2 bb = Bf[ks * 32 + lane];

        uint32_t a0 = wpair(ga.x, ga.y, na, Qxa, Qya, Qba);
        uint32_t a1 = wpair(ga.x, ga.y, na, Qxb, Qyb, Qbb);
        uint32_t a2 = wpair(gb.x, gb.y, nb, Qxa, Qya, Qba);
        uint32_t a3 = wpair(gb.x, gb.y, nb, Qxb, Qyb, Qbb);

        mma16(c0, c1, c2, c3, a0, a1, a2, a3, bb.x, bb.y);
        mma16(e0, e1, e2, e3, a0, a1, a2, a3, bones, bones);
    }

    // ---- combine K-halves ----
    float4* scr = (float4*)(smem + OFF_SCR);
    if (half == 1) {
        scr[(g * 32 + lane) * 2 + 0] = make_float4(c0, c1, c2, c3);
        scr[(g * 32 + lane) * 2 + 1] = make_float4(e0, e2, 0.f, 0.f);
    }
    __syncthreads();
    if (half == 0) {
        float4 f = scr[(g * 32 + lane) * 2 + 0];
        float4 e = scr[(g * 32 + lane) * 2 + 1];
        c0 += f.x; c1 += f.y; c2 += f.z; c3 += f.w;
        e0 += e.x; e2 += e.y;

        // density lives on lanes with j==0; broadcast within quad
        float da = __shfl_sync(0xffffffffu, e0, lane & ~3);
        float db = __shfl_sync(0xffffffffu, e2, lane & ~3);
        float inva = 1.0f / (da + 1e-8f);
        float invb = 1.0f / (db + 1e-8f);

        const int f0 = 2 * j;
        float* oa = out + ((size_t)b * NQ + qg) * 9;
        float* ob = oa + 8 * 9;
        oa[f0] = c0 * inva; oa[f0 + 1] = c1 * inva;
        ob[f0] = c2 * invb; ob[f0 + 1] = c3 * invb;
        if (j == 0) { oa[8] = da; ob[8] = db; }
    }
}

extern "C" void kernel_launch(void* const* d_in, const int* in_sizes, int n_in,
                              void* d_out, int out_size) {
    const float* xq  = (const float*)d_in[0];
    const float* xc  = (const float*)d_in[1];
    const float* yc  = (const float*)d_in[2];
    const float* lls = (const float*)d_in[3];
    float* out = (float*)d_out;

    cudaFuncSetAttribute(setconv_h16, cudaFuncAttributeMaxDynamicSharedMemorySize,
                         SMEM_TOTAL);
    setconv_h16<<<BB * (NQ / QT), NTHREADS, SMEM_TOTAL>>>(xq, xc, yc, lls, out);
}